// round 16
// baseline (speedup 1.0000x reference)
#include <cuda_runtime.h>
#include <mma.h>
#include <cuda_fp16.h>
#include <cstdint>

using namespace nvcuda;

#define DM 1024
#define NH 16
#define DH 64
#define NB 2
#define NS 2048
#define MTOT (NB*NS)
#define SCALE_LOG2E 0.18033688011112042f   // log2(e)/8

// Scratch: head-split projections [B, H, S, DH], fp16 (Q pre-scaled)
__device__ __half g_Q[NB*NH*NS*DH];
__device__ __half g_K[NB*NH*NS*DH];
__device__ __half g_V[NB*NH*NS*DH];
// Pre-converted fp16 inputs
__device__ __half g_Xc[3ull*MTOT*DM];
__device__ __half g_Wc[3ull*DM*DM];
// Split-K partials (fp32)
__device__ float g_Op[2ull*NB*NH*16*128*64];
__device__ float g_Lp[2ull*NB*NH*16*128];

__device__ __forceinline__ float ex2f(float x) {
    float r;
    asm("ex2.approx.f32 %0, %1;" : "=f"(r) : "f"(x));
    return r;
}
__device__ __forceinline__ uint32_t smem_u32(const void* p) {
    uint32_t a;
    asm("{ .reg .u64 t; cvta.to.shared.u64 t, %1; cvt.u32.u64 %0, t; }" : "=r"(a) : "l"(p));
    return a;
}
__device__ __forceinline__ void cpa16(uint32_t dst, const void* src) {
    asm volatile("cp.async.cg.shared.global [%0], [%1], 16;" :: "r"(dst), "l"(src) : "memory");
}
#define CP_COMMIT() asm volatile("cp.async.commit_group;" ::: "memory")
#define CP_WAIT0()  asm volatile("cp.async.wait_group 0;" ::: "memory")
#define CP_WAIT1()  asm volatile("cp.async.wait_group 1;" ::: "memory")

__device__ __forceinline__ uint2 f4_to_h4(float4 v) {
    __half2 h0 = __float22half2_rn(make_float2(v.x, v.y));
    __half2 h1 = __float22half2_rn(make_float2(v.z, v.w));
    uint2 u;
    u.x = *(uint32_t*)&h0; u.y = *(uint32_t*)&h1;
    return u;
}

typedef wmma::fragment<wmma::matrix_a, 16, 16, 16, __half, wmma::row_major> FragAh;
typedef wmma::fragment<wmma::matrix_b, 16, 16, 16, __half, wmma::col_major> FragBch;
typedef wmma::fragment<wmma::matrix_b, 16, 16, 16, __half, wmma::row_major> FragBrh;
typedef wmma::fragment<wmma::accumulator, 16, 16, 16, float> FragCh;

// ---------------------------------------------------------------------------
// Pre-convert all six inputs fp32 -> fp16 in one launch.
// ---------------------------------------------------------------------------
#define NX4 (MTOT*DM/4)
#define NW4 (DM*DM/4)
__global__ __launch_bounds__(256) void cvt_all(
    const float* __restrict__ q, const float* __restrict__ k, const float* __restrict__ v,
    const float* __restrict__ wq, const float* __restrict__ wk, const float* __restrict__ wv)
{
    const long i = (long)blockIdx.x * 256 + threadIdx.x;
    if (i < 3L*NX4) {
        const int t = (int)(i / NX4), off = (int)(i - (long)t*NX4);
        const float* s = (t == 0) ? q : (t == 1) ? k : v;
        ((uint2*)g_Xc)[i] = f4_to_h4(((const float4*)s)[off]);
    } else {
        const long j = i - 3L*NX4;
        if (j < 3L*NW4) {
            const int t = (int)(j / NW4), off = (int)(j - (long)t*NW4);
            const float* s = (t == 0) ? wq : (t == 1) ? wk : wv;
            ((uint2*)g_Wc)[j] = f4_to_h4(((const float4*)s)[off]);
        }
    }
}

// ---------------------------------------------------------------------------
// Projection: C = X @ W^T (fp16 wmma, fp32 accum). Tile 128x128, 8 warps
// (4m x 2n), warp 32x64, k staged 64 wide, TRIPLE-buffered cp.async
// (wait_group 1 -> each load has 2 compute stages of latency cover).
// smem (halves): A[3][128][72] | B[3][128][72]; epilogue Cs fp32 overlays.
// ---------------------------------------------------------------------------
#define LD_PJ 72
#define PJ_BUF (128*LD_PJ)            // 9216 halves per buffer
#define PJ_SMEM (6*PJ_BUF*2)          // 110592 B
#define CS_LD 132

__global__ __launch_bounds__(256, 2) void proj_tc()
{
    extern __shared__ __half smh[];
    __half* As = smh;                     // 3 buffers
    __half* Bs = smh + 3*PJ_BUF;          // 3 buffers
    const uint32_t as_u = smem_u32(As);
    const uint32_t bs_u = smem_u32(Bs);

    const __half* X = g_Xc + (size_t)blockIdx.z * MTOT * DM;
    const __half* W = g_Wc + (size_t)blockIdx.z * DM * DM;
    __half* out = (blockIdx.z == 0) ? g_Q : (blockIdx.z == 1) ? g_K : g_V;

    const int tid = threadIdx.x;
    const int wid = tid >> 5;
    const int mw = wid & 3, nw = wid >> 2;
    const int bm = blockIdx.x * 128, bn = blockIdx.y * 128;

    FragCh c[2][4];
#pragma unroll
    for (int i = 0; i < 2; i++)
#pragma unroll
        for (int j = 0; j < 4; j++) wmma::fill_fragment(c[i][j], 0.0f);

    // Prologue: issue stages 0 and 1 (separate commit groups)
#pragma unroll
    for (int st = 0; st < 2; st++) {
        const int k0 = st * 64;
        const uint32_t ab = as_u + st * PJ_BUF * 2;
        const uint32_t bb = bs_u + st * PJ_BUF * 2;
        for (int c2 = tid; c2 < 1024; c2 += 256) {
            const int row = c2 >> 3, col = (c2 & 7) << 3;
            cpa16(ab + (row*LD_PJ + col)*2, X + (size_t)(bm + row)*DM + k0 + col);
            cpa16(bb + (row*LD_PJ + col)*2, W + (size_t)(bn + row)*DM + k0 + col);
        }
        CP_COMMIT();
    }

    const int NSTG = DM / 64;
    for (int s = 0; s < NSTG; s++) {
        if (s < NSTG - 1) CP_WAIT1(); else CP_WAIT0();
        __syncthreads();
        if (s + 2 < NSTG) {
            const int k0 = (s + 2) * 64;
            const int bi = (s + 2) % 3;
            const uint32_t ab = as_u + bi * PJ_BUF * 2;
            const uint32_t bb = bs_u + bi * PJ_BUF * 2;
            for (int c2 = tid; c2 < 1024; c2 += 256) {
                const int row = c2 >> 3, col = (c2 & 7) << 3;
                cpa16(ab + (row*LD_PJ + col)*2, X + (size_t)(bm + row)*DM + k0 + col);
                cpa16(bb + (row*LD_PJ + col)*2, W + (size_t)(bn + row)*DM + k0 + col);
            }
            CP_COMMIT();
        }
        const __half* Ab = As + (s % 3) * PJ_BUF;
        const __half* Bb = Bs + (s % 3) * PJ_BUF;
#pragma unroll
        for (int ks = 0; ks < 4; ks++) {
            FragAh a[2];
#pragma unroll
            for (int i = 0; i < 2; i++)
                wmma::load_matrix_sync(a[i], Ab + (32*mw + 16*i)*LD_PJ + ks*16, LD_PJ);
#pragma unroll
            for (int j = 0; j < 4; j++) {
                FragBch bfr;
                wmma::load_matrix_sync(bfr, Bb + (64*nw + 16*j)*LD_PJ + ks*16, LD_PJ);
                wmma::mma_sync(c[0][j], a[0], bfr, c[0][j]);
                wmma::mma_sync(c[1][j], a[1], bfr, c[1][j]);
            }
        }
        __syncthreads();   // compute done before buffer (s)%3 reused at s+3
    }

    // Epilogue: stage C (fp32) into smem overlay, scatter fp16 head-split
    float* Cs = (float*)smh;
#pragma unroll
    for (int i = 0; i < 2; i++)
#pragma unroll
        for (int j = 0; j < 4; j++)
            wmma::store_matrix_sync(Cs + (32*mw + 16*i)*CS_LD + 64*nw + 16*j,
                                    c[i][j], CS_LD, wmma::mem_row_major);
    __syncthreads();

    {
        const float scl = (blockIdx.z == 0) ? SCALE_LOG2E : 1.0f;
        const int r = tid >> 1;
        const int coff = (tid & 1) * 64;
        const int m = bm + r;
        const int b_ = m >> 11, s_ = m & (NS - 1);
        const int n0 = bn + coff;
        const int h = n0 >> 6;
        __half* op = out + ((size_t)(b_*NH + h)*NS + s_)*DH;
#pragma unroll
        for (int q = 0; q < 8; q++) {
            float4 v0 = *(const float4*)&Cs[r*CS_LD + coff + q*8];
            float4 v1 = *(const float4*)&Cs[r*CS_LD + coff + q*8 + 4];
            v0.x *= scl; v0.y *= scl; v0.z *= scl; v0.w *= scl;
            v1.x *= scl; v1.y *= scl; v1.z *= scl; v1.w *= scl;
            uint2 u0 = f4_to_h4(v0), u1 = f4_to_h4(v1);
            uint4 u = make_uint4(u0.x, u0.y, u1.x, u1.y);
            *(uint4*)(op + q*8) = u;
        }
    }
}

// ---------------------------------------------------------------------------
// Attention, split-K x2, fp16/fp32-accum, TRIPLE-buffered K/V cp.async.
// In-register P (probe-verified), MUFU exp.
// smem (halves): K[3][128][72] | V[3][128][72] | P[8][32][72] | Ls(f32 128)
// Epilogue Os (fp32, 2*128*68) overlays the K/V region.
// ---------------------------------------------------------------------------
#define LD_KH 72
#define KVBUF (128*LD_KH)                 // 9216 halves per buffer
#define OFF_VH (3*KVBUF)                  // 27648
#define OFF_PH (OFF_VH + 3*KVBUF)         // 55296
#define OFF_LS (OFF_PH + 8*32*LD_KH)      // 73728 (halves)
#define AT_FLOATS_H (OFF_LS + 256)        // halves total
#define AT_SMEM (AT_FLOATS_H*2)           // 147968 B
#define LD_O 68

__global__ __launch_bounds__(256) void attn_tc()
{
    extern __shared__ __half smh[];
    __half* Ks = smh;
    __half* Vs = smh + OFF_VH;
    __half* Ps = smh + OFF_PH;
    float* Ls = (float*)(smh + OFF_LS);
    float* Os = (float*)smh;              // epilogue overlay on K/V region
    const uint32_t ks_u = smem_u32(Ks);
    const uint32_t vs_u = smem_u32(Vs);

    const int tid = threadIdx.x;
    const int wid = tid >> 5, lane = tid & 31;
    const int mw = wid & 3, nw = wid >> 2;
    const int qt = blockIdx.x >> 1, half_ = blockIdx.x & 1;
    const int h = blockIdx.y, b = blockIdx.z;
    const int kt0 = half_ * 8, kt1 = kt0 + 8;

    const __half* Qg = g_Q + ((size_t)(b*NH + h)*NS + qt*128) * DH;
    const __half* Kg = g_K + (size_t)(b*NH + h)*NS * DH;
    const __half* Vg = g_V + (size_t)(b*NH + h)*NS * DH;

    // Prologue: issue K/V tiles kt0 and kt0+1 into buffers 0,1
#pragma unroll
    for (int t = 0; t < 2; t++) {
        const size_t key0 = (size_t)(kt0 + t) * 128 * DH;
        const uint32_t kb = ks_u + t * KVBUF * 2;
        const uint32_t vb = vs_u + t * KVBUF * 2;
        for (int c2 = tid; c2 < 1024; c2 += 256) {
            const int row = c2 >> 3, col = (c2 & 7) << 3;
            cpa16(kb + (row*LD_KH + col)*2, Kg + key0 + (size_t)row*DH + col);
            cpa16(vb + (row*LD_KH + col)*2, Vg + key0 + (size_t)row*DH + col);
        }
        CP_COMMIT();
    }

    __half* Pw = Ps + wid*32*LD_KH;

    // --- Probes ---
    int rowof[8], colof[8];
    bool inreg;
    {
        __half* Aq = Pw;
        __half* Bq = Pw + 256;
        for (int e = lane; e < 256; e += 32) {
            const int k2 = e & 15, mn = e >> 4;
            Aq[e] = __float2half((k2 == 0) ? (float)mn : (k2 == 1) ? 1.0f : 0.0f);
            Bq[e] = __float2half((k2 == 0) ? 16.0f : (k2 == 1) ? (float)mn : 0.0f);
        }
        __syncwarp();
        FragAh pa; wmma::load_matrix_sync(pa, Aq, 16);
        FragBch pb; wmma::load_matrix_sync(pb, Bq, 16);
        FragCh pc; wmma::fill_fragment(pc, 0.0f);
        wmma::mma_sync(pc, pa, pb, pc);
#pragma unroll
        for (int e = 0; e < 8; e++) {
            const int v = (int)pc.x[e];
            rowof[e] = v >> 4; colof[e] = v & 15;
        }
        __syncwarp();
        for (int e = lane; e < 256; e += 32) Aq[e] = __float2half((float)e);
        __syncwarp();
        FragAh pq; wmma::load_matrix_sync(pq, Aq, 16);
        inreg = true;
#pragma unroll
        for (int e = 0; e < (int)FragAh::num_elements; e++) {
            const int v = (int)__half2float(pq.x[e]);
            inreg = inreg && ((v >> 4) == rowof[e & 7]) && ((v & 15) == colof[e & 7]);
        }
    }
    __syncthreads();

    // Stage Q into Ps region; init Ls
    for (int c2 = tid; c2 < 1024; c2 += 256) {
        const int row = c2 >> 3, col = (c2 & 7) << 3;
        *(uint4*)(smh + OFF_PH + row*LD_KH + col) =
            *(const uint4*)(Qg + (size_t)row*DH + col);
    }
    if (tid < 128) Ls[tid] = 0.0f;
    __syncthreads();
    FragAh qa[2][4];
#pragma unroll
    for (int i = 0; i < 2; i++)
#pragma unroll
        for (int ks = 0; ks < 4; ks++)
            wmma::load_matrix_sync(qa[i][ks],
                smh + OFF_PH + (32*mw + 16*i)*LD_KH + ks*16, LD_KH);

    FragCh o[2][4];
#pragma unroll
    for (int i = 0; i < 2; i++)
#pragma unroll
        for (int j = 0; j < 4; j++) wmma::fill_fragment(o[i][j], 0.0f);
    float lacc[2][8];
#pragma unroll
    for (int i = 0; i < 2; i++)
#pragma unroll
        for (int e = 0; e < 8; e++) lacc[i][e] = 0.0f;

    __half pf[2][4][8];   // in-register P: [i][col-tile][C-elem]

    for (int kt = kt0; kt < kt1; kt++) {
        const int t = kt - kt0;
        if (kt < kt1 - 1) CP_WAIT1(); else CP_WAIT0();
        __syncthreads();
        if (kt + 2 < kt1) {
            const size_t key0 = (size_t)(kt + 2) * 128 * DH;
            const int bi = (t + 2) % 3;
            const uint32_t kb = ks_u + bi * KVBUF * 2;
            const uint32_t vb = vs_u + bi * KVBUF * 2;
            for (int c2 = tid; c2 < 1024; c2 += 256) {
                const int row = c2 >> 3, col = (c2 & 7) << 3;
                cpa16(kb + (row*LD_KH + col)*2, Kg + key0 + (size_t)row*DH + col);
                cpa16(vb + (row*LD_KH + col)*2, Vg + key0 + (size_t)row*DH + col);
            }
            CP_COMMIT();
        }
        const __half* Kb = Ks + (t % 3) * KVBUF;
        const __half* Vb = Vs + (t % 3) * KVBUF;

        // S = Q @ K^T on warp's 64-key half, two 32-col groups
#pragma unroll
        for (int jh = 0; jh < 2; jh++) {
            FragCh s[2][2];
#pragma unroll
            for (int i = 0; i < 2; i++)
#pragma unroll
                for (int j = 0; j < 2; j++) wmma::fill_fragment(s[i][j], 0.0f);
#pragma unroll
            for (int ks = 0; ks < 4; ks++) {
                FragBch kb2[2];
#pragma unroll
                for (int j = 0; j < 2; j++)
                    wmma::load_matrix_sync(kb2[j],
                        Kb + (64*nw + 32*jh + 16*j)*LD_KH + ks*16, LD_KH);
#pragma unroll
                for (int j = 0; j < 2; j++) {
                    wmma::mma_sync(s[0][j], qa[0][ks], kb2[j], s[0][j]);
                    wmma::mma_sync(s[1][j], qa[1][ks], kb2[j], s[1][j]);
                }
            }
#pragma unroll
            for (int i = 0; i < 2; i++)
#pragma unroll
                for (int j = 0; j < 2; j++) {
                    if (inreg) {
#pragma unroll
                        for (int e = 0; e < 8; e++) {
                            float p = ex2f(s[i][j].x[e]);
                            lacc[i][e] += p;
                            pf[i][2*jh + j][e] = __float2half(p);
                        }
                    } else {
#pragma unroll
                        for (int e = 0; e < 8; e++) {
                            float p = ex2f(s[i][j].x[e]);
                            lacc[i][e] += p;
                            Pw[(16*i + rowof[e])*LD_KH + 32*jh + 16*j + colof[e]] =
                                __float2half(p);
                        }
                    }
                }
        }
        if (!inreg) __syncwarp();

        // O += P @ V over this warp's 64-key slice
#pragma unroll
        for (int ks = 0; ks < 4; ks++) {
            FragAh pa2[2];
            if (inreg) {
#pragma unroll
                for (int i = 0; i < 2; i++)
#pragma unroll
                    for (int e = 0; e < (int)FragAh::num_elements; e++)
                        pa2[i].x[e] = pf[i][ks][e & 7];
            } else {
#pragma unroll
                for (int i = 0; i < 2; i++)
                    wmma::load_matrix_sync(pa2[i], Pw + (16*i)*LD_KH + ks*16, LD_KH);
            }
#pragma unroll
            for (int j = 0; j < 4; j++) {
                FragBrh vbf;
                wmma::load_matrix_sync(vbf, Vb + (64*nw + ks*16)*LD_KH + 16*j, LD_KH);
                wmma::mma_sync(o[0][j], pa2[0], vbf, o[0][j]);
                wmma::mma_sync(o[1][j], pa2[1], vbf, o[1][j]);
            }
        }
        __syncthreads();   // buffer t%3 reads done before reuse at t+3
    }

#pragma unroll
    for (int i = 0; i < 2; i++)
#pragma unroll
        for (int e = 0; e < 8; e++)
            atomicAdd(&Ls[32*mw + 16*i + rowof[e]], lacc[i][e]);
    {
        float* Ob = Os + nw*128*LD_O;
#pragma unroll
        for (int i = 0; i < 2; i++)
#pragma unroll
            for (int j = 0; j < 4; j++)
                wmma::store_matrix_sync(Ob + (32*mw + 16*i)*LD_O + 16*j,
                                        o[i][j], LD_O, wmma::mem_row_major);
    }
    __syncthreads();

    {
        const size_t pbase = (size_t)(b*NH + h)*16 + qt;
        const int rr = tid >> 1, ch = tid & 1;
        const float* O0 = Os + rr*LD_O;
        const float* O1 = Os + 128*LD_O + rr*LD_O;
        float* op = g_Op + (size_t)half_*NB*NH*16*128*64 + pbase*8192 + rr*64 + ch*32;
        const int c0 = ch * 32;
#pragma unroll
        for (int q = 0; q < 8; q++) {
            float4 v0 = *(const float4*)&O0[c0 + q*4];
            float4 v1 = *(const float4*)&O1[c0 + q*4];
            float4 v = make_float4(v0.x + v1.x, v0.y + v1.y, v0.z + v1.z, v0.w + v1.w);
            *(float4*)(op + q*4) = v;
        }
        if (tid < 128)
            g_Lp[(size_t)half_*NB*NH*16*128 + pbase*128 + tid] = Ls[tid];
    }
}

// ---------------------------------------------------------------------------
// Combine: out = (O0 + O1) / (l0 + l1). 4x parallel (8 floats/thread).
// ---------------------------------------------------------------------------
__global__ __launch_bounds__(256) void combine_k(float* __restrict__ out)
{
    const int tid = threadIdx.x;
    const int qt = blockIdx.x >> 2, sub = blockIdx.x & 3;
    const int h = blockIdx.y, b = blockIdx.z;
    const size_t pbase = (size_t)(b*NH + h)*16 + qt;
    const size_t HOFS = (size_t)NB*NH*16*128*64;
    const size_t LOFS = (size_t)NB*NH*16*128;
    const int rr = sub*32 + (tid >> 3);
    const int c0 = (tid & 7) * 8;
    const float l = g_Lp[pbase*128 + rr] + g_Lp[LOFS + pbase*128 + rr];
    const float inv = 1.0f / l;
    const float* P0 = g_Op + pbase*8192 + rr*64 + c0;
    const float* P1 = P0 + HOFS;
    float* op = out + ((size_t)b*NS + qt*128 + rr)*DM + h*DH + c0;
#pragma unroll
    for (int q = 0; q < 2; q++) {
        float4 v0 = *(const float4*)(P0 + q*4);
        float4 v1 = *(const float4*)(P1 + q*4);
        float4 v = make_float4((v0.x + v1.x)*inv, (v0.y + v1.y)*inv,
                               (v0.z + v1.z)*inv, (v0.w + v1.w)*inv);
        *(float4*)(op + q*4) = v;
    }
}

extern "C" void kernel_launch(void* const* d_in, const int* in_sizes, int n_in,
                              void* d_out, int out_size)
{
    const float* q  = (const float*)d_in[0];
    const float* k  = (const float*)d_in[1];
    const float* v  = (const float*)d_in[2];
    const float* wq = (const float*)d_in[3];
    const float* wk = (const float*)d_in[4];
    const float* wv = (const float*)d_in[5];
    float* out = (float*)d_out;

    const long NCVT = 3L*NX4 + 3L*NW4;
    cvt_all<<<(unsigned)((NCVT + 255)/256), 256>>>(q, k, v, wq, wk, wv);

    cudaFuncSetAttribute(proj_tc, cudaFuncAttributeMaxDynamicSharedMemorySize, PJ_SMEM);
    cudaFuncSetAttribute(attn_tc, cudaFuncAttributeMaxDynamicSharedMemorySize, AT_SMEM);

    dim3 pg(MTOT / 128, DM / 128, 3);
    proj_tc<<<pg, 256, PJ_SMEM>>>();

    dim3 ag(32, NH, NB);   // x = qt*2 + kv-half
    attn_tc<<<ag, 256, AT_SMEM>>>();

    dim3 cg(64, NH, NB);   // x = qt*4 + row-quarter
    combine_k<<<cg, 256>>>(out);
}

// round 17
// speedup vs baseline: 1.5193x; 1.5193x over previous
#include <cuda_runtime.h>
#include <mma.h>
#include <cuda_fp16.h>
#include <cstdint>

using namespace nvcuda;

#define DM 1024
#define NH 16
#define DH 64
#define NB 2
#define NS 2048
#define MTOT (NB*NS)
#define SCALE_LOG2E 0.18033688011112042f   // log2(e)/8

__device__ __half g_Q[NB*NH*NS*DH];
__device__ __half g_K[NB*NH*NS*DH];
__device__ __half g_V[NB*NH*NS*DH];
__device__ __half g_Xc[3ull*MTOT*DM];
__device__ __half g_Wc[3ull*DM*DM];
__device__ float g_Op[2ull*NB*NH*16*128*64];
__device__ float g_Lp[2ull*NB*NH*16*128];

__device__ __forceinline__ float ex2f(float x) {
    float r;
    asm("ex2.approx.f32 %0, %1;" : "=f"(r) : "f"(x));
    return r;
}
__device__ __forceinline__ uint32_t smem_u32(const void* p) {
    uint32_t a;
    asm("{ .reg .u64 t; cvta.to.shared.u64 t, %1; cvt.u32.u64 %0, t; }" : "=r"(a) : "l"(p));
    return a;
}
__device__ __forceinline__ void cpa16(uint32_t dst, const void* src) {
    asm volatile("cp.async.cg.shared.global [%0], [%1], 16;" :: "r"(dst), "l"(src) : "memory");
}
#define CP_COMMIT() asm volatile("cp.async.commit_group;" ::: "memory")
#define CP_WAIT0()  asm volatile("cp.async.wait_group 0;" ::: "memory")
#define CP_WAIT1()  asm volatile("cp.async.wait_group 1;" ::: "memory")

__device__ __forceinline__ uint2 f4_to_h4(float4 v) {
    __half2 h0 = __float22half2_rn(make_float2(v.x, v.y));
    __half2 h1 = __float22half2_rn(make_float2(v.z, v.w));
    uint2 u;
    u.x = *(uint32_t*)&h0; u.y = *(uint32_t*)&h1;
    return u;
}

typedef wmma::fragment<wmma::matrix_a, 16, 16, 16, __half, wmma::row_major> FragAh;
typedef wmma::fragment<wmma::matrix_b, 16, 16, 16, __half, wmma::col_major> FragBch;
typedef wmma::fragment<wmma::matrix_b, 16, 16, 16, __half, wmma::row_major> FragBrh;
typedef wmma::fragment<wmma::accumulator, 16, 16, 16, float> FragCh;

// ---------------------------------------------------------------------------
// Pre-convert all six inputs fp32 -> fp16 in one launch.
// ---------------------------------------------------------------------------
#define NX4 (MTOT*DM/4)
#define NW4 (DM*DM/4)
__global__ __launch_bounds__(256) void cvt_all(
    const float* __restrict__ q, const float* __restrict__ k, const float* __restrict__ v,
    const float* __restrict__ wq, const float* __restrict__ wk, const float* __restrict__ wv)
{
    const long i = (long)blockIdx.x * 256 + threadIdx.x;
    if (i < 3L*NX4) {
        const int t = (int)(i / NX4), off = (int)(i - (long)t*NX4);
        const float* s = (t == 0) ? q : (t == 1) ? k : v;
        ((uint2*)g_Xc)[i] = f4_to_h4(((const float4*)s)[off]);
    } else {
        const long j = i - 3L*NX4;
        if (j < 3L*NW4) {
            const int t = (int)(j / NW4), off = (int)(j - (long)t*NW4);
            const float* s = (t == 0) ? wq : (t == 1) ? wk : wv;
            ((uint2*)g_Wc)[j] = f4_to_h4(((const float4*)s)[off]);
        }
    }
}

// ---------------------------------------------------------------------------
// Projection: C = X @ W^T (fp16 wmma, fp32 accum). Tile 128x128, 8 warps
// (4m x 2n), warp 32x64, k staged 64 wide, triple-buffered cp.async with
// wait_group 1 and ONE barrier per stage.
// smem (halves): A[3][128][72] | B[3][128][72]; epilogue Cs fp32 overlays.
// ---------------------------------------------------------------------------
#define LD_PJ 72
#define PJ_BUF (128*LD_PJ)
#define PJ_SMEM (6*PJ_BUF*2)          // 110592 B
#define CS_LD 132

__global__ __launch_bounds__(256, 2) void proj_tc()
{
    extern __shared__ __half smh[];
    __half* As = smh;
    __half* Bs = smh + 3*PJ_BUF;
    const uint32_t as_u = smem_u32(As);
    const uint32_t bs_u = smem_u32(Bs);

    const __half* X = g_Xc + (size_t)blockIdx.z * MTOT * DM;
    const __half* W = g_Wc + (size_t)blockIdx.z * DM * DM;
    __half* out = (blockIdx.z == 0) ? g_Q : (blockIdx.z == 1) ? g_K : g_V;

    const int tid = threadIdx.x;
    const int wid = tid >> 5;
    const int mw = wid & 3, nw = wid >> 2;
    const int bm = blockIdx.x * 128, bn = blockIdx.y * 128;

    FragCh c[2][4];
#pragma unroll
    for (int i = 0; i < 2; i++)
#pragma unroll
        for (int j = 0; j < 4; j++) wmma::fill_fragment(c[i][j], 0.0f);

    // Prologue: issue stages 0 and 1
#pragma unroll
    for (int st = 0; st < 2; st++) {
        const int k0 = st * 64;
        const uint32_t ab = as_u + st * PJ_BUF * 2;
        const uint32_t bb = bs_u + st * PJ_BUF * 2;
        for (int c2 = tid; c2 < 1024; c2 += 256) {
            const int row = c2 >> 3, col = (c2 & 7) << 3;
            cpa16(ab + (row*LD_PJ + col)*2, X + (size_t)(bm + row)*DM + k0 + col);
            cpa16(bb + (row*LD_PJ + col)*2, W + (size_t)(bn + row)*DM + k0 + col);
        }
        CP_COMMIT();
    }

    const int NSTG = DM / 64;
    for (int s = 0; s < NSTG; s++) {
        if (s < NSTG - 1) CP_WAIT1(); else CP_WAIT0();
        __syncthreads();   // compute of s-1 done everywhere; buffer (s+2)%3 free
        if (s + 2 < NSTG) {
            const int k0 = (s + 2) * 64;
            const int bi = (s + 2) % 3;
            const uint32_t ab = as_u + bi * PJ_BUF * 2;
            const uint32_t bb = bs_u + bi * PJ_BUF * 2;
            for (int c2 = tid; c2 < 1024; c2 += 256) {
                const int row = c2 >> 3, col = (c2 & 7) << 3;
                cpa16(ab + (row*LD_PJ + col)*2, X + (size_t)(bm + row)*DM + k0 + col);
                cpa16(bb + (row*LD_PJ + col)*2, W + (size_t)(bn + row)*DM + k0 + col);
            }
            CP_COMMIT();
        }
        const __half* Ab = As + (s % 3) * PJ_BUF;
        const __half* Bb = Bs + (s % 3) * PJ_BUF;
#pragma unroll
        for (int ks = 0; ks < 4; ks++) {
            FragAh a[2];
#pragma unroll
            for (int i = 0; i < 2; i++)
                wmma::load_matrix_sync(a[i], Ab + (32*mw + 16*i)*LD_PJ + ks*16, LD_PJ);
#pragma unroll
            for (int j = 0; j < 4; j++) {
                FragBch bfr;
                wmma::load_matrix_sync(bfr, Bb + (64*nw + 16*j)*LD_PJ + ks*16, LD_PJ);
                wmma::mma_sync(c[0][j], a[0], bfr, c[0][j]);
                wmma::mma_sync(c[1][j], a[1], bfr, c[1][j]);
            }
        }
    }
    __syncthreads();

    float* Cs = (float*)smh;
#pragma unroll
    for (int i = 0; i < 2; i++)
#pragma unroll
        for (int j = 0; j < 4; j++)
            wmma::store_matrix_sync(Cs + (32*mw + 16*i)*CS_LD + 64*nw + 16*j,
                                    c[i][j], CS_LD, wmma::mem_row_major);
    __syncthreads();

    {
        const float scl = (blockIdx.z == 0) ? SCALE_LOG2E : 1.0f;
        const int r = tid >> 1;
        const int coff = (tid & 1) * 64;
        const int m = bm + r;
        const int b_ = m >> 11, s_ = m & (NS - 1);
        const int n0 = bn + coff;
        const int h = n0 >> 6;
        __half* op = out + ((size_t)(b_*NH + h)*NS + s_)*DH;
#pragma unroll
        for (int q = 0; q < 8; q++) {
            float4 v0 = *(const float4*)&Cs[r*CS_LD + coff + q*8];
            float4 v1 = *(const float4*)&Cs[r*CS_LD + coff + q*8 + 4];
            v0.x *= scl; v0.y *= scl; v0.z *= scl; v0.w *= scl;
            v1.x *= scl; v1.y *= scl; v1.z *= scl; v1.w *= scl;
            uint2 u0 = f4_to_h4(v0), u1 = f4_to_h4(v1);
            uint4 u = make_uint4(u0.x, u0.y, u1.x, u1.y);
            *(uint4*)(op + q*8) = u;
        }
    }
}

// ---------------------------------------------------------------------------
// Attention, split-K x2, fp16/fp32-accum, triple-buffered K/V cp.async with
// wait_group 1 and ONE barrier per stage. In-register P (probe), MUFU exp.
// smem (halves): K[3][128][72] | V[3][128][72] | P[8][32][72] | Ls(f32 128)
// Epilogue Os (fp32) overlays the K/V region.
// ---------------------------------------------------------------------------
#define LD_KH 72
#define KVBUF (128*LD_KH)
#define OFF_VH (3*KVBUF)
#define OFF_PH (OFF_VH + 3*KVBUF)
#define OFF_LS (OFF_PH + 8*32*LD_KH)
#define AT_FLOATS_H (OFF_LS + 256)
#define AT_SMEM (AT_FLOATS_H*2)           // 147968 B
#define LD_O 68

__global__ __launch_bounds__(256) void attn_tc()
{
    extern __shared__ __half smh[];
    __half* Ks = smh;
    __half* Vs = smh + OFF_VH;
    __half* Ps = smh + OFF_PH;
    float* Ls = (float*)(smh + OFF_LS);
    float* Os = (float*)smh;
    const uint32_t ks_u = smem_u32(Ks);
    const uint32_t vs_u = smem_u32(Vs);

    const int tid = threadIdx.x;
    const int wid = tid >> 5, lane = tid & 31;
    const int mw = wid & 3, nw = wid >> 2;
    const int qt = blockIdx.x >> 1, half_ = blockIdx.x & 1;
    const int h = blockIdx.y, b = blockIdx.z;
    const int kt0 = half_ * 8, kt1 = kt0 + 8;

    const __half* Qg = g_Q + ((size_t)(b*NH + h)*NS + qt*128) * DH;
    const __half* Kg = g_K + (size_t)(b*NH + h)*NS * DH;
    const __half* Vg = g_V + (size_t)(b*NH + h)*NS * DH;

    // Prologue: issue K/V tiles kt0 and kt0+1 into buffers 0,1
#pragma unroll
    for (int t = 0; t < 2; t++) {
        const size_t key0 = (size_t)(kt0 + t) * 128 * DH;
        const uint32_t kb = ks_u + t * KVBUF * 2;
        const uint32_t vb = vs_u + t * KVBUF * 2;
        for (int c2 = tid; c2 < 1024; c2 += 256) {
            const int row = c2 >> 3, col = (c2 & 7) << 3;
            cpa16(kb + (row*LD_KH + col)*2, Kg + key0 + (size_t)row*DH + col);
            cpa16(vb + (row*LD_KH + col)*2, Vg + key0 + (size_t)row*DH + col);
        }
        CP_COMMIT();
    }

    __half* Pw = Ps + wid*32*LD_KH;

    // --- Probes ---
    int rowof[8], colof[8];
    bool inreg;
    {
        __half* Aq = Pw;
        __half* Bq = Pw + 256;
        for (int e = lane; e < 256; e += 32) {
            const int k2 = e & 15, mn = e >> 4;
            Aq[e] = __float2half((k2 == 0) ? (float)mn : (k2 == 1) ? 1.0f : 0.0f);
            Bq[e] = __float2half((k2 == 0) ? 16.0f : (k2 == 1) ? (float)mn : 0.0f);
        }
        __syncwarp();
        FragAh pa; wmma::load_matrix_sync(pa, Aq, 16);
        FragBch pb; wmma::load_matrix_sync(pb, Bq, 16);
        FragCh pc; wmma::fill_fragment(pc, 0.0f);
        wmma::mma_sync(pc, pa, pb, pc);
#pragma unroll
        for (int e = 0; e < 8; e++) {
            const int v = (int)pc.x[e];
            rowof[e] = v >> 4; colof[e] = v & 15;
        }
        __syncwarp();
        for (int e = lane; e < 256; e += 32) Aq[e] = __float2half((float)e);
        __syncwarp();
        FragAh pq; wmma::load_matrix_sync(pq, Aq, 16);
        inreg = true;
#pragma unroll
        for (int e = 0; e < (int)FragAh::num_elements; e++) {
            const int v = (int)__half2float(pq.x[e]);
            inreg = inreg && ((v >> 4) == rowof[e & 7]) && ((v & 15) == colof[e & 7]);
        }
    }
    __syncthreads();

    // Stage Q into Ps region; init Ls
    for (int c2 = tid; c2 < 1024; c2 += 256) {
        const int row = c2 >> 3, col = (c2 & 7) << 3;
        *(uint4*)(smh + OFF_PH + row*LD_KH + col) =
            *(const uint4*)(Qg + (size_t)row*DH + col);
    }
    if (tid < 128) Ls[tid] = 0.0f;
    __syncthreads();
    FragAh qa[2][4];
#pragma unroll
    for (int i = 0; i < 2; i++)
#pragma unroll
        for (int ks = 0; ks < 4; ks++)
            wmma::load_matrix_sync(qa[i][ks],
                smh + OFF_PH + (32*mw + 16*i)*LD_KH + ks*16, LD_KH);

    FragCh o[2][4];
#pragma unroll
    for (int i = 0; i < 2; i++)
#pragma unroll
        for (int j = 0; j < 4; j++) wmma::fill_fragment(o[i][j], 0.0f);
    float lacc[2][8];
#pragma unroll
    for (int i = 0; i < 2; i++)
#pragma unroll
        for (int e = 0; e < 8; e++) lacc[i][e] = 0.0f;

    __half pf[2][4][8];

    for (int kt = kt0; kt < kt1; kt++) {
        const int t = kt - kt0;
        if (kt < kt1 - 1) CP_WAIT1(); else CP_WAIT0();
        __syncthreads();   // compute of t-1 done; buffer (t+2)%3 free
        if (kt + 2 < kt1) {
            const size_t key0 = (size_t)(kt + 2) * 128 * DH;
            const int bi = (t + 2) % 3;
            const uint32_t kb = ks_u + bi * KVBUF * 2;
            const uint32_t vb = vs_u + bi * KVBUF * 2;
            for (int c2 = tid; c2 < 1024; c2 += 256) {
                const int row = c2 >> 3, col = (c2 & 7) << 3;
                cpa16(kb + (row*LD_KH + col)*2, Kg + key0 + (size_t)row*DH + col);
                cpa16(vb + (row*LD_KH + col)*2, Vg + key0 + (size_t)row*DH + col);
            }
            CP_COMMIT();
        }
        const __half* Kb = Ks + (t % 3) * KVBUF;
        const __half* Vb = Vs + (t % 3) * KVBUF;

        // S = Q @ K^T on warp's 64-key half, two 32-col groups
#pragma unroll
        for (int jh = 0; jh < 2; jh++) {
            FragCh s[2][2];
#pragma unroll
            for (int i = 0; i < 2; i++)
#pragma unroll
                for (int j = 0; j < 2; j++) wmma::fill_fragment(s[i][j], 0.0f);
#pragma unroll
            for (int ks = 0; ks < 4; ks++) {
                FragBch kb2[2];
#pragma unroll
                for (int j = 0; j < 2; j++)
                    wmma::load_matrix_sync(kb2[j],
                        Kb + (64*nw + 32*jh + 16*j)*LD_KH + ks*16, LD_KH);
#pragma unroll
                for (int j = 0; j < 2; j++) {
                    wmma::mma_sync(s[0][j], qa[0][ks], kb2[j], s[0][j]);
                    wmma::mma_sync(s[1][j], qa[1][ks], kb2[j], s[1][j]);
                }
            }
#pragma unroll
            for (int i = 0; i < 2; i++)
#pragma unroll
                for (int j = 0; j < 2; j++) {
                    if (inreg) {
#pragma unroll
                        for (int e = 0; e < 8; e++) {
                            float p = ex2f(s[i][j].x[e]);
                            lacc[i][e] += p;
                            pf[i][2*jh + j][e] = __float2half(p);
                        }
                    } else {
#pragma unroll
                        for (int e = 0; e < 8; e++) {
                            float p = ex2f(s[i][j].x[e]);
                            lacc[i][e] += p;
                            Pw[(16*i + rowof[e])*LD_KH + 32*jh + 16*j + colof[e]] =
                                __float2half(p);
                        }
                    }
                }
        }
        if (!inreg) __syncwarp();

        // O += P @ V over this warp's 64-key slice
#pragma unroll
        for (int ks = 0; ks < 4; ks++) {
            FragAh pa2[2];
            if (inreg) {
#pragma unroll
                for (int i = 0; i < 2; i++)
#pragma unroll
                    for (int e = 0; e < (int)FragAh::num_elements; e++)
                        pa2[i].x[e] = pf[i][ks][e & 7];
            } else {
#pragma unroll
                for (int i = 0; i < 2; i++)
                    wmma::load_matrix_sync(pa2[i], Pw + (16*i)*LD_KH + ks*16, LD_KH);
            }
#pragma unroll
            for (int j = 0; j < 4; j++) {
                FragBrh vbf;
                wmma::load_matrix_sync(vbf, Vb + (64*nw + ks*16)*LD_KH + 16*j, LD_KH);
                wmma::mma_sync(o[0][j], pa2[0], vbf, o[0][j]);
                wmma::mma_sync(o[1][j], pa2[1], vbf, o[1][j]);
            }
        }
    }

    __syncthreads();   // all K/V reads done before Os overlay
#pragma unroll
    for (int i = 0; i < 2; i++)
#pragma unroll
        for (int e = 0; e < 8; e++)
            atomicAdd(&Ls[32*mw + 16*i + rowof[e]], lacc[i][e]);
    {
        float* Ob = Os + nw*128*LD_O;
#pragma unroll
        for (int i = 0; i < 2; i++)
#pragma unroll
            for (int j = 0; j < 4; j++)
                wmma::store_matrix_sync(Ob + (32*mw + 16*i)*LD_O + 16*j,
                                        o[i][j], LD_O, wmma::mem_row_major);
    }
    __syncthreads();

    {
        const size_t pbase = (size_t)(b*NH + h)*16 + qt;
        const int rr = tid >> 1, ch = tid & 1;
        const float* O0 = Os + rr*LD_O;
        const float* O1 = Os + 128*LD_O + rr*LD_O;
        float* op = g_Op + (size_t)half_*NB*NH*16*128*64 + pbase*8192 + rr*64 + ch*32;
        const int c0 = ch * 32;
#pragma unroll
        for (int q = 0; q < 8; q++) {
            float4 v0 = *(const float4*)&O0[c0 + q*4];
            float4 v1 = *(const float4*)&O1[c0 + q*4];
            float4 v = make_float4(v0.x + v1.x, v0.y + v1.y, v0.z + v1.z, v0.w + v1.w);
            *(float4*)(op + q*4) = v;
        }
        if (tid < 128)
            g_Lp[(size_t)half_*NB*NH*16*128 + pbase*128 + tid] = Ls[tid];
    }
}

// ---------------------------------------------------------------------------
// Combine: out = (O0 + O1) / (l0 + l1). 4x parallel (8 floats/thread).
// ---------------------------------------------------------------------------
__global__ __launch_bounds__(256) void combine_k(float* __restrict__ out)
{
    const int tid = threadIdx.x;
    const int qt = blockIdx.x >> 2, sub = blockIdx.x & 3;
    const int h = blockIdx.y, b = blockIdx.z;
    const size_t pbase = (size_t)(b*NH + h)*16 + qt;
    const size_t HOFS = (size_t)NB*NH*16*128*64;
    const size_t LOFS = (size_t)NB*NH*16*128;
    const int rr = sub*32 + (tid >> 3);
    const int c0 = (tid & 7) * 8;
    const float l = g_Lp[pbase*128 + rr] + g_Lp[LOFS + pbase*128 + rr];
    const float inv = 1.0f / l;
    const float* P0 = g_Op + pbase*8192 + rr*64 + c0;
    const float* P1 = P0 + HOFS;
    float* op = out + ((size_t)b*NS + qt*128 + rr)*DM + h*DH + c0;
#pragma unroll
    for (int q = 0; q < 2; q++) {
        float4 v0 = *(const float4*)(P0 + q*4);
        float4 v1 = *(const float4*)(P1 + q*4);
        float4 v = make_float4((v0.x + v1.x)*inv, (v0.y + v1.y)*inv,
                               (v0.z + v1.z)*inv, (v0.w + v1.w)*inv);
        *(float4*)(op + q*4) = v;
    }
}

extern "C" void kernel_launch(void* const* d_in, const int* in_sizes, int n_in,
                              void* d_out, int out_size)
{
    const float* q  = (const float*)d_in[0];
    const float* k  = (const float*)d_in[1];
    const float* v  = (const float*)d_in[2];
    const float* wq = (const float*)d_in[3];
    const float* wk = (const float*)d_in[4];
    const float* wv = (const float*)d_in[5];
    float* out = (float*)d_out;

    const long NCVT = 3L*NX4 + 3L*NW4;
    cvt_all<<<(unsigned)((NCVT + 255)/256), 256>>>(q, k, v, wq, wk, wv);

    cudaFuncSetAttribute(proj_tc, cudaFuncAttributeMaxDynamicSharedMemorySize, PJ_SMEM);
    cudaFuncSetAttribute(attn_tc, cudaFuncAttributeMaxDynamicSharedMemorySize, AT_SMEM);

    dim3 pg(MTOT / 128, DM / 128, 3);
    proj_tc<<<pg, 256, PJ_SMEM>>>();

    dim3 ag(32, NH, NB);   // x = qt*2 + kv-half
    attn_tc<<<ag, 256, AT_SMEM>>>();

    dim3 cg(64, NH, NB);   // x = qt*4 + row-quarter
    combine_k<<<cg, 256>>>(out);
}